// round 7
// baseline (speedup 1.0000x reference)
#include <cuda_runtime.h>
#include <cuda_fp16.h>
#include <cstdint>

#define TOKENS 16384
#define DIMS   128
#define SLOTS  64

// ---------------- device globals ---------------------------------------------
__device__ __align__(16) float g_C[DIMS * SLOTS];        // C[d][m], pre-scaled
__device__ __align__(16) float g_d0[SLOTS];               // bias, pre-scaled
__device__ float g_attnT[SLOTS * TOKENS];                 // attn [m][t] fp32
__device__ __align__(16) unsigned g_opsH[SLOTS * DIMS * 64]; // fp16 ops, swizzled image (2MB)

// ---------------- helpers ----------------------------------------------------
__device__ __forceinline__ uint32_t smem_u32(const void* p) {
    uint32_t a;
    asm("{ .reg .u64 t; cvta.to.shared.u64 t, %1; cvt.u32.u64 %0, t; }" : "=r"(a) : "l"(p));
    return a;
}
__device__ __forceinline__ unsigned packh2(float lo, float hi) {
    unsigned u;
    asm("{ .reg .f16 l, h; cvt.rn.f16.f32 l, %1; cvt.rn.f16.f32 h, %2; mov.b32 %0, {l, h}; }"
        : "=r"(u) : "f"(lo), "f"(hi));
    return u;
}
__device__ __forceinline__ void ldsm4(unsigned* r, uint32_t addr) {
    asm volatile("ldmatrix.sync.aligned.m8n8.x4.shared.b16 {%0,%1,%2,%3}, [%4];"
                 : "=r"(r[0]), "=r"(r[1]), "=r"(r[2]), "=r"(r[3]) : "r"(addr));
}
__device__ __forceinline__ void mma16816(float* c, const unsigned* a, unsigned b0, unsigned b1) {
    asm volatile(
        "mma.sync.aligned.m16n8k16.row.col.f32.f16.f16.f32 "
        "{%0,%1,%2,%3}, {%4,%5,%6,%7}, {%8,%9}, {%0,%1,%2,%3};"
        : "+f"(c[0]), "+f"(c[1]), "+f"(c[2]), "+f"(c[3])
        : "r"(a[0]), "r"(a[1]), "r"(a[2]), "r"(a[3]), "r"(b0), "r"(b1));
}
// first-ks variant: C comes from persistent zero registers (no zero-init cost)
__device__ __forceinline__ void mma16816_zc(float* d, const unsigned* a, unsigned b0, unsigned b1,
                                            float z0, float z1, float z2, float z3) {
    asm volatile(
        "mma.sync.aligned.m16n8k16.row.col.f32.f16.f16.f32 "
        "{%0,%1,%2,%3}, {%4,%5,%6,%7}, {%8,%9}, {%10,%11,%12,%13};"
        : "=f"(d[0]), "=f"(d[1]), "=f"(d[2]), "=f"(d[3])
        : "r"(a[0]), "r"(a[1]), "r"(a[2]), "r"(a[3]), "r"(b0), "r"(b1),
          "f"(z0), "f"(z1), "f"(z2), "f"(z3));
}
__device__ __forceinline__ void cpasync16(uint32_t dst, const void* src) {
    asm volatile("cp.async.cg.shared.global [%0], [%1], 16;" :: "r"(dst), "l"(src) : "memory");
}

// ---------------- kernel A: ops->fp16 swizzled image + C/d0 precompute -------
__global__ void kA(const float* __restrict__ ops, const float* __restrict__ Wq,
                   const float* __restrict__ bq, const float* __restrict__ MK) {
    __shared__ float mk[128];
    __shared__ float part[128];
    const int b = blockIdx.x, tid = threadIdx.x;
    if (b < 128) {
#pragma unroll
        for (int i = 0; i < 4; i++) {
            int idx = b * 1024 + i * 256 + tid;      // 16B-chunk id, 131072 total
            int m = idx >> 11, c = idx & 2047;
            int d = c >> 4, ch = c & 15;
            const float4* s = (const float4*)(ops + m * 16384 + d * 128 + ch * 8);
            float4 v0 = s[0], v1 = s[1];
            uint4 o;
            o.x = packh2(v0.x, v0.y); o.y = packh2(v0.z, v0.w);
            o.z = packh2(v1.x, v1.y); o.w = packh2(v1.z, v1.w);
            unsigned dst = (unsigned)m * 8192u + (unsigned)d * 64u
                         + (unsigned)((ch ^ (d & 7)) << 2);   // u32 units
            *(uint4*)(g_opsH + dst) = o;
        }
    } else {
        const int m = b - 128;                        // 0..63
        if (tid < 128) mk[tid] = MK[m * 128 + tid];
        __syncthreads();
        const int d = tid & 127, half = tid >> 7;
        const int e0 = half * 64;
        float s = 0.f;
#pragma unroll 8
        for (int e = e0; e < e0 + 64; e++) s += Wq[e * 128 + d] * mk[e];
        if (half) part[d] = s;
        __syncthreads();
        const float inv = 0.08838834764831845f;
        if (!half) g_C[d * 64 + m] = (s + part[d]) * inv;
        if (tid == 0) {
            float s2 = 0.f;
#pragma unroll 8
            for (int e = 0; e < 128; e++) s2 += bq[e] * mk[e];
            g_d0[m] = s2 * inv;
        }
    }
}

// ---------------- kernel 1: logits + softmax -> g_attnT (scalar, proven) -----
__global__ void k1_attn(const float* __restrict__ x) {
    extern __shared__ float sm1[];
    float* xs = sm1;               // [32][132]
    float* Cs = xs + 32 * 132;     // [128][64]
    float* ls = Cs + 128 * 64;     // [32][65]
    const int tid = threadIdx.x;
    const int T0 = blockIdx.x * 32;
#pragma unroll
    for (int i = tid; i < 32 * 32; i += 128) {
        int t = i >> 5, q = i & 31;
        *(float4*)(xs + t * 132 + q * 4) = *(const float4*)(x + (T0 + t) * 128 + q * 4);
    }
#pragma unroll
    for (int i = tid; i < 2048; i += 128) ((float4*)Cs)[i] = ((const float4*)g_C)[i];
    __syncthreads();
    const int t = tid >> 2, mg = tid & 3;
    float acc[16];
#pragma unroll
    for (int j = 0; j < 16; j++) acc[j] = g_d0[mg * 16 + j];
    for (int d = 0; d < 128; d++) {
        float xv = xs[t * 132 + d];
#pragma unroll
        for (int j4 = 0; j4 < 4; j4++) {
            float4 c4 = *(const float4*)(Cs + d * 64 + mg * 16 + j4 * 4);
            acc[j4*4+0] += xv*c4.x; acc[j4*4+1] += xv*c4.y;
            acc[j4*4+2] += xv*c4.z; acc[j4*4+3] += xv*c4.w;
        }
    }
#pragma unroll
    for (int j = 0; j < 16; j++) ls[t * 65 + mg * 16 + j] = acc[j];
    __syncthreads();
    if (tid < 32) {
        float mx = -1e30f;
#pragma unroll 8
        for (int m = 0; m < 64; m++) mx = fmaxf(mx, ls[tid * 65 + m]);
        float s = 0.f;
#pragma unroll 8
        for (int m = 0; m < 64; m++) { float e = __expf(ls[tid*65+m]-mx); ls[tid*65+m] = e; s += e; }
        float iv = 1.f / s;
#pragma unroll 8
        for (int m = 0; m < 64; m++) ls[tid * 65 + m] *= iv;
    }
    __syncthreads();
#pragma unroll
    for (int i = tid; i < 2048; i += 128) {
        int tt = i & 31, m = i >> 5;
        g_attnT[m * TOKENS + T0 + tt] = ls[tt * 65 + m];
    }
}

// ---------------- kernel 2: fp16 mma, attn applied on OUTPUT (fp32) ----------
// 148 CTAs x 512 thr; CTA = ng*16 tokens (7 or 6 groups) x 128 dims.
// Warps: 4 rows x 4 cols; row owns groups {row, row+4}; col owns 32 dims.
// Per slot: z = x @ ops[m]^T (unscaled, zero-C first mma), acc += attn * z.
// SMEM: xs 28KB | attnP (float2) 28KB | B dbl buf 2x32KB  = 122880 B.
__global__ __launch_bounds__(512) void k2_gemm(const float* __restrict__ x,
                                               float* __restrict__ out) {
    extern __shared__ __align__(16) unsigned char smraw[];
    const uint32_t XS = smem_u32(smraw);
    const uint32_t AP = XS + 28672u;
    const uint32_t BB = XS + 57344u;

    const int tid = threadIdx.x, l = tid & 31, w = tid >> 5;
    const int rowi = w >> 2, wd = (w & 3) * 32;
    const int cta = blockIdx.x;
    const int ng = (cta < 136) ? 7 : 6;
    const int t0 = (cta < 136) ? cta * 112 : 15232 + (cta - 136) * 96;
    const int ntok = ng * 16;

    // ---- stage x tile: fp32 -> fp16, XOR-swizzled [t][e] ----
    for (int idx = tid; idx < ntok * 16; idx += 512) {
        int row = idx >> 4, ch = idx & 15;
        const float4* sp = (const float4*)(x + (size_t)(t0 + row) * 128 + ch * 8);
        float4 v0 = sp[0], v1 = sp[1];
        uint4 o;
        o.x = packh2(v0.x, v0.y); o.y = packh2(v0.z, v0.w);
        o.z = packh2(v1.x, v1.y); o.w = packh2(v1.z, v1.w);
        asm volatile("st.shared.v4.b32 [%0], {%1,%2,%3,%4};"
                     :: "r"(XS + (unsigned)(row * 256) + (unsigned)((ch ^ (row & 7)) << 4)),
                        "r"(o.x), "r"(o.y), "r"(o.z), "r"(o.w) : "memory");
    }
    // ---- stage attnP: float2 (attn[t], attn[t+8]), layout [m][56] ----
    for (int idx = tid; idx < 64 * 56; idx += 512) {
        int m = idx / 56, p = idx - m * 56;
        int g = p >> 3;
        if (g < ng) {
            int tl = g * 16 + (p & 7);
            float lo = g_attnT[m * TOKENS + t0 + tl];
            float hi = g_attnT[m * TOKENS + t0 + tl + 8];
            asm volatile("st.shared.v2.b32 [%0], {%1,%2};"
                         :: "r"(AP + (unsigned)idx * 8), "r"(__float_as_uint(lo)),
                            "r"(__float_as_uint(hi)) : "memory");
        }
    }
    // ---- prologue: B(0) ----
#pragma unroll
    for (int i = 0; i < 4; i++) {
        int idx = tid + i * 512;
        cpasync16(BB + idx * 16, (const char*)g_opsH + idx * 16);
    }
    asm volatile("cp.async.commit_group;" ::: "memory");
    __syncthreads();

    const int nj = (rowi + 4 < ng) ? 2 : 1;
    float acc[2][4][4] = {};
    const float zc = 0.f;   // persistent zero C operands

    for (int m = 0; m < 64; m++) {
        asm volatile("cp.async.wait_group 0;" ::: "memory");
        __syncthreads();
        if (m < 63) {
            const char* src = (const char*)g_opsH + (size_t)(m + 1) * 32768;
            uint32_t dst = BB + (unsigned)((m + 1) & 1) * 32768u;
#pragma unroll
            for (int i = 0; i < 4; i++) {
                int idx = tid + i * 512;
                cpasync16(dst + idx * 16, src + idx * 16);
            }
            asm volatile("cp.async.commit_group;" ::: "memory");
        }

        float z[2][4][4];
        const uint32_t Bb = BB + (unsigned)(m & 1) * 32768u;
#pragma unroll
        for (int ks = 0; ks < 8; ks++) {
            const int c0 = ks * 2;
            unsigned bf[2][4];
            {
                int n_off = ((l >> 4) << 3) + (l & 7);
                int chB = c0 + ((l >> 3) & 1);
#pragma unroll
                for (int np = 0; np < 2; np++) {
                    int row = wd + np * 16 + n_off;
                    uint32_t addr = Bb + row * 256 + ((chB ^ (row & 7)) << 4);
                    ldsm4(bf[np], addr);
                }
            }
            int r_off = l & 15;
            int chA = c0 + (l >> 4);
#pragma unroll
            for (int j = 0; j < 2; j++) {
                if (j < nj) {
                    int g = rowi + 4 * j;
                    int row = g * 16 + r_off;
                    uint32_t addr = XS + row * 256 + ((chA ^ (r_off & 7)) << 4);
                    unsigned a[4];
                    ldsm4(a, addr);
#pragma unroll
                    for (int nt = 0; nt < 4; nt++) {
                        if (ks == 0)
                            mma16816_zc(z[j][nt], a, bf[nt >> 1][(nt & 1) * 2],
                                        bf[nt >> 1][(nt & 1) * 2 + 1], zc, zc, zc, zc);
                        else
                            mma16816(z[j][nt], a, bf[nt >> 1][(nt & 1) * 2],
                                     bf[nt >> 1][(nt & 1) * 2 + 1]);
                    }
                }
            }
        }
        // fold attn (fp32) into output accumulators
#pragma unroll
        for (int j = 0; j < 2; j++) {
            if (j < nj) {
                int g = rowi + 4 * j;
                float2 at;
                asm volatile("ld.shared.v2.b32 {%0,%1}, [%2];"
                             : "=r"(*(unsigned*)&at.x), "=r"(*(unsigned*)&at.y)
                             : "r"(AP + (unsigned)(m * 56 + g * 8 + (l >> 2)) * 8));
#pragma unroll
                for (int nt = 0; nt < 4; nt++) {
                    acc[j][nt][0] = fmaf(at.x, z[j][nt][0], acc[j][nt][0]);
                    acc[j][nt][1] = fmaf(at.x, z[j][nt][1], acc[j][nt][1]);
                    acc[j][nt][2] = fmaf(at.y, z[j][nt][2], acc[j][nt][2]);
                    acc[j][nt][3] = fmaf(at.y, z[j][nt][3], acc[j][nt][3]);
                }
            }
        }
    }

    // ---- writeback ----
#pragma unroll
    for (int j = 0; j < 2; j++) {
        if (j < nj) {
            int g = rowi + 4 * j;
            int row = t0 + g * 16 + (l >> 2);
#pragma unroll
            for (int nt = 0; nt < 4; nt++) {
                int col = wd + nt * 8 + (l & 3) * 2;
                *(float2*)(out + (size_t)row * 128 + col) =
                    make_float2(acc[j][nt][0], acc[j][nt][1]);
                *(float2*)(out + (size_t)(row + 8) * 128 + col) =
                    make_float2(acc[j][nt][2], acc[j][nt][3]);
            }
        }
    }
}

// ---------------------------------------------------------------------------
extern "C" void kernel_launch(void* const* d_in, const int* in_sizes, int n_in,
                              void* d_out, int out_size) {
    const float* x   = (const float*)d_in[0];   // [4,4096,128]
    const float* MK  = (const float*)d_in[1];   // [64,128]
    const float* ops = (const float*)d_in[2];   // [64,128,128]
    const float* Wq  = (const float*)d_in[3];   // [128,128]
    const float* bq  = (const float*)d_in[4];   // [128]
    float* out = (float*)d_out;

    const int smem1 = (32 * 132 + 128 * 64 + 32 * 65) * 4;  // 57984
    const int smem2 = 122880;
    cudaFuncSetAttribute(k1_attn, cudaFuncAttributeMaxDynamicSharedMemorySize, smem1);
    cudaFuncSetAttribute(k2_gemm, cudaFuncAttributeMaxDynamicSharedMemorySize, smem2);

    kA<<<192, 256>>>(ops, Wq, bq, MK);
    k1_attn<<<TOKENS / 32, 128, smem1>>>(x);
    k2_gemm<<<148, 512, smem2>>>(x, out);
}

// round 8
// speedup vs baseline: 1.2328x; 1.2328x over previous
#include <cuda_runtime.h>
#include <cuda_fp16.h>
#include <cstdint>

#define TOKENS 16384
#define DIMS   128
#define SLOTS  64

// ---------------- device globals ---------------------------------------------
__device__ __align__(16) float g_C[DIMS * SLOTS];        // C[d][m], pre-scaled
__device__ __align__(16) float g_d0[SLOTS];               // bias, pre-scaled
__device__ __align__(16) unsigned g_opsH[SLOTS * DIMS * 64]; // fp16 ops, swizzled (2MB)

// ---------------- helpers ----------------------------------------------------
__device__ __forceinline__ uint32_t smem_u32(const void* p) {
    uint32_t a;
    asm("{ .reg .u64 t; cvta.to.shared.u64 t, %1; cvt.u32.u64 %0, t; }" : "=r"(a) : "l"(p));
    return a;
}
__device__ __forceinline__ unsigned packh2(float lo, float hi) {
    unsigned u;
    asm("{ .reg .f16 l, h; cvt.rn.f16.f32 l, %1; cvt.rn.f16.f32 h, %2; mov.b32 %0, {l, h}; }"
        : "=r"(u) : "f"(lo), "f"(hi));
    return u;
}
__device__ __forceinline__ unsigned hmul2(unsigned a, unsigned b) {
    unsigned r; asm("mul.rn.f16x2 %0, %1, %2;" : "=r"(r) : "r"(a), "r"(b)); return r;
}
__device__ __forceinline__ void ldsm4(unsigned* r, uint32_t addr) {
    asm volatile("ldmatrix.sync.aligned.m8n8.x4.shared.b16 {%0,%1,%2,%3}, [%4];"
                 : "=r"(r[0]), "=r"(r[1]), "=r"(r[2]), "=r"(r[3]) : "r"(addr));
}
__device__ __forceinline__ void mma16816(float* c, const unsigned* a, unsigned b0, unsigned b1) {
    asm volatile(
        "mma.sync.aligned.m16n8k16.row.col.f32.f16.f16.f32 "
        "{%0,%1,%2,%3}, {%4,%5,%6,%7}, {%8,%9}, {%0,%1,%2,%3};"
        : "+f"(c[0]), "+f"(c[1]), "+f"(c[2]), "+f"(c[3])
        : "r"(a[0]), "r"(a[1]), "r"(a[2]), "r"(a[3]), "r"(b0), "r"(b1));
}
__device__ __forceinline__ void cpasync16(uint32_t dst, const void* src) {
    asm volatile("cp.async.cg.shared.global [%0], [%1], 16;" :: "r"(dst), "l"(src) : "memory");
}

// ---------------- kernel A: ops->fp16 swizzled image + C/d0 precompute -------
// blocks 0..255: convert ops (512 chunks each); blocks 256..319: C[:,m].
__global__ void kA(const float* __restrict__ ops, const float* __restrict__ Wq,
                   const float* __restrict__ bq, const float* __restrict__ MK) {
    __shared__ float mk[128];
    __shared__ float part[128];
    const int b = blockIdx.x, tid = threadIdx.x;
    if (b < 256) {
#pragma unroll
        for (int i = 0; i < 2; i++) {
            int idx = b * 512 + i * 256 + tid;       // 16B-chunk id, 131072 total
            int m = idx >> 11, c = idx & 2047;
            int d = c >> 4, ch = c & 15;
            const float4* s = (const float4*)(ops + m * 16384 + d * 128 + ch * 8);
            float4 v0 = s[0], v1 = s[1];
            uint4 o;
            o.x = packh2(v0.x, v0.y); o.y = packh2(v0.z, v0.w);
            o.z = packh2(v1.x, v1.y); o.w = packh2(v1.z, v1.w);
            unsigned dst = (unsigned)m * 8192u + (unsigned)d * 64u
                         + (unsigned)((ch ^ (d & 7)) << 2);   // u32 units
            *(uint4*)(g_opsH + dst) = o;
        }
    } else {
        const int m = b - 256;                        // 0..63
        if (tid < 128) mk[tid] = MK[m * 128 + tid];
        __syncthreads();
        const int d = tid & 127, half = tid >> 7;
        const int e0 = half * 64;
        float s = 0.f;
#pragma unroll 8
        for (int e = e0; e < e0 + 64; e++) s += Wq[e * 128 + d] * mk[e];
        if (half) part[d] = s;
        __syncthreads();
        const float inv = 0.08838834764831845f;
        if (!half) g_C[d * 64 + m] = (s + part[d]) * inv;
        if (tid == 0) {
            float s2 = 0.f;
#pragma unroll 8
            for (int e = 0; e < 128; e++) s2 += bq[e] * mk[e];
            g_d0[m] = s2 * inv;
        }
    }
}

// ---------------- kernel 2: fused attn + fp16 mma, 2 CTAs/SM -----------------
// 296 CTAs x 256 thr. CTA = ng*16 tokens (ng=4 for cta<136 else 3) x 128 dims.
// Warps: 2 rows x 4 cols; row r owns groups {r, r+2}; col owns 32 dims.
// SMEM: xs 16KB | AP 8KB | B dbl buf 2x32KB = 90112 B.  (Cs/ls borrow B bufs)
__global__ __launch_bounds__(256, 2) void k2_fused(const float* __restrict__ x,
                                                   float* __restrict__ out) {
    extern __shared__ __align__(16) unsigned char smraw[];
    const uint32_t XS = smem_u32(smraw);
    const uint32_t AP = XS + 16384u;
    const uint32_t BB = XS + 24576u;
    float* Cs = (float*)(smraw + 24576);            // B buf0 (32KB) during attn
    float* ls = (float*)(smraw + 24576 + 32768);    // B buf1 (16.6KB) during attn

    const int tid = threadIdx.x, l = tid & 31, w = tid >> 5;
    const int rowi = w >> 2, wd = (w & 3) * 32;
    const int cta = blockIdx.x;
    const int ng = (cta < 136) ? 4 : 3;
    const int t0 = (cta < 136) ? cta * 64 : 8704 + (cta - 136) * 48;
    const int ntok = ng * 16;

    // ---- stage x tile: fp32 -> fp16, XOR-swizzled [t][e] ----
    for (int idx = tid; idx < ntok * 16; idx += 256) {
        int row = idx >> 4, ch = idx & 15;
        const float4* sp = (const float4*)(x + (size_t)(t0 + row) * 128 + ch * 8);
        float4 v0 = sp[0], v1 = sp[1];
        uint4 o;
        o.x = packh2(v0.x, v0.y); o.y = packh2(v0.z, v0.w);
        o.z = packh2(v1.x, v1.y); o.w = packh2(v1.z, v1.w);
        asm volatile("st.shared.v4.b32 [%0], {%1,%2,%3,%4};"
                     :: "r"(XS + (unsigned)(row * 256) + (unsigned)((ch ^ (row & 7)) << 4)),
                        "r"(o.x), "r"(o.y), "r"(o.z), "r"(o.w) : "memory");
    }
    // ---- stage C into B buf0 ----
    for (int idx = tid; idx < 2048; idx += 256)
        ((float4*)Cs)[idx] = ((const float4*)g_C)[idx];
    __syncthreads();

    // ---- logits: fp32, x re-read from gmem (L2 hot) ----
    {
        const int t = tid >> 2, mg = tid & 3;
        if (t < ntok) {
            float acc[16];
#pragma unroll
            for (int j = 0; j < 16; j++) acc[j] = g_d0[mg * 16 + j];
            const float4* xp = (const float4*)(x + (size_t)(t0 + t) * 128);
#pragma unroll 4
            for (int d4 = 0; d4 < 32; d4++) {
                float4 xv4 = xp[d4];
                const float* cb = Cs + (d4 * 4) * 64 + mg * 16;
#pragma unroll
                for (int q = 0; q < 4; q++) {
                    float xv = (q == 0) ? xv4.x : (q == 1) ? xv4.y : (q == 2) ? xv4.z : xv4.w;
                    const float4* c4 = (const float4*)(cb + q * 64);
#pragma unroll
                    for (int j4 = 0; j4 < 4; j4++) {
                        float4 cc = c4[j4];
                        acc[j4*4+0] = fmaf(xv, cc.x, acc[j4*4+0]);
                        acc[j4*4+1] = fmaf(xv, cc.y, acc[j4*4+1]);
                        acc[j4*4+2] = fmaf(xv, cc.z, acc[j4*4+2]);
                        acc[j4*4+3] = fmaf(xv, cc.w, acc[j4*4+3]);
                    }
                }
            }
#pragma unroll
            for (int j = 0; j < 16; j++) ls[t * 65 + mg * 16 + j] = acc[j];
        }
    }
    __syncthreads();
    // ---- softmax per token (threads 0..ntok-1) ----
    if (tid < ntok) {
        float mx = -1e30f;
#pragma unroll 8
        for (int m = 0; m < 64; m++) mx = fmaxf(mx, ls[tid * 65 + m]);
        float s = 0.f;
#pragma unroll 8
        for (int m = 0; m < 64; m++) { float e = __expf(ls[tid*65+m]-mx); ls[tid*65+m] = e; s += e; }
        float iv = 1.f / s;
#pragma unroll 8
        for (int m = 0; m < 64; m++) ls[tid * 65 + m] *= iv;
    }
    __syncthreads();
    // ---- pack attn pairs (t, t+8) fp16x2 into AP [m][32] ----
    for (int idx = tid; idx < 64 * 32; idx += 256) {
        int m = idx >> 5, p = idx & 31;
        int g = p >> 3;
        if (g < ng) {
            int tl = g * 16 + (p & 7);
            unsigned u = packh2(ls[tl * 65 + m], ls[(tl + 8) * 65 + m]);
            asm volatile("st.shared.b32 [%0], %1;" :: "r"(AP + (unsigned)idx * 4), "r"(u) : "memory");
        }
    }
    __syncthreads();   // ls/Cs dead; B buffers free

    // ---- prologue: B(0) into buf0 ----
#pragma unroll
    for (int i = 0; i < 8; i++) {
        int idx = tid + i * 256;
        cpasync16(BB + idx * 16, (const char*)g_opsH + idx * 16);
    }
    asm volatile("cp.async.commit_group;" ::: "memory");

    float acc[2][4][4] = {};

    for (int m = 0; m < 64; m++) {
        asm volatile("cp.async.wait_group 0;" ::: "memory");
        __syncthreads();
        if (m < 63) {
            const char* src = (const char*)g_opsH + (size_t)(m + 1) * 32768;
            uint32_t dst = BB + (unsigned)((m + 1) & 1) * 32768u;
#pragma unroll
            for (int i = 0; i < 8; i++) {
                int idx = tid + i * 256;
                cpasync16(dst + idx * 16, src + idx * 16);
            }
            asm volatile("cp.async.commit_group;" ::: "memory");
        }

        // attn splats for this slot (per owned group)
        unsigned lo2[2], hi2[2];
#pragma unroll
        for (int j = 0; j < 2; j++) {
            int g = rowi + 2 * j;
            if (g < ng) {
                unsigned pu;
                asm volatile("ld.shared.b32 %0, [%1];"
                             : "=r"(pu) : "r"(AP + (unsigned)(m * 32 + g * 8 + (l >> 2)) * 4));
                asm("prmt.b32 %0, %1, %1, 0x1010;" : "=r"(lo2[j]) : "r"(pu));
                asm("prmt.b32 %0, %1, %1, 0x3232;" : "=r"(hi2[j]) : "r"(pu));
            }
        }

        const uint32_t Bb = BB + (unsigned)(m & 1) * 32768u;
#pragma unroll
        for (int ks = 0; ks < 8; ks++) {
            const int c0 = ks * 2;
            unsigned bf[2][4];
            {
                int n_off = ((l >> 4) << 3) + (l & 7);
                int chB = c0 + ((l >> 3) & 1);
#pragma unroll
                for (int np = 0; np < 2; np++) {
                    int row = wd + np * 16 + n_off;
                    uint32_t addr = Bb + row * 256 + ((chB ^ (row & 7)) << 4);
                    ldsm4(bf[np], addr);
                }
            }
            int r_off = l & 15;
            int chA = c0 + (l >> 4);
#pragma unroll
            for (int j = 0; j < 2; j++) {
                int g = rowi + 2 * j;
                if (g < ng) {
                    int row = g * 16 + r_off;
                    uint32_t addr = XS + row * 256 + ((chA ^ (r_off & 7)) << 4);
                    unsigned a[4];
                    ldsm4(a, addr);
                    a[0] = hmul2(a[0], lo2[j]);
                    a[1] = hmul2(a[1], hi2[j]);
                    a[2] = hmul2(a[2], lo2[j]);
                    a[3] = hmul2(a[3], hi2[j]);
#pragma unroll
                    for (int nt = 0; nt < 4; nt++)
                        mma16816(acc[j][nt], a, bf[nt >> 1][(nt & 1) * 2],
                                 bf[nt >> 1][(nt & 1) * 2 + 1]);
                }
            }
        }
    }

    // ---- writeback ----
#pragma unroll
    for (int j = 0; j < 2; j++) {
        int g = rowi + 2 * j;
        if (g < ng) {
            int row = t0 + g * 16 + (l >> 2);
#pragma unroll
            for (int nt = 0; nt < 4; nt++) {
                int col = wd + nt * 8 + (l & 3) * 2;
                *(float2*)(out + (size_t)row * 128 + col) =
                    make_float2(acc[j][nt][0], acc[j][nt][1]);
                *(float2*)(out + (size_t)(row + 8) * 128 + col) =
                    make_float2(acc[j][nt][2], acc[j][nt][3]);
            }
        }
    }
}

// ---------------------------------------------------------------------------
extern "C" void kernel_launch(void* const* d_in, const int* in_sizes, int n_in,
                              void* d_out, int out_size) {
    const float* x   = (const float*)d_in[0];   // [4,4096,128]
    const float* MK  = (const float*)d_in[1];   // [64,128]
    const float* ops = (const float*)d_in[2];   // [64,128,128]
    const float* Wq  = (const float*)d_in[3];   // [128,128]
    const float* bq  = (const float*)d_in[4];   // [128]
    float* out = (float*)d_out;

    const int smem2 = 90112;
    cudaFuncSetAttribute(k2_fused, cudaFuncAttributeMaxDynamicSharedMemorySize, smem2);

    kA<<<320, 256>>>(ops, Wq, bq, MK);
    k2_fused<<<296, 256, smem2>>>(x, out);
}